// round 9
// baseline (speedup 1.0000x reference)
#include <cuda_runtime.h>
#include <cstdint>

#define N_NODES  100000
#define N_EDGES  1200000
#define N_GRAPHS 1024
#define F        64
#define BN_EPS   1e-5f
#define SCAN_BLOCKS 98          // ceil(100000/1024)

// ---------------- device scratch (no allocations allowed) ----------------
// Self-cleaning invariant: g_cnt, g_scan_pack, g_hg are ALL-ZERO before and
// after every kernel_launch execution (static zero-init covers the first).
__device__ float4 g_agg4[N_NODES * (F / 4)];   // neighbor MEANS (fully overwritten)
__device__ int    g_cnt[N_NODES];              // in-degree   (zeroed by k_gather)
__device__ int    g_off[N_NODES];              // CSR offsets (fully overwritten)
__device__ int    g_cursor[N_NODES];           // scatter cursors (fully overwritten)
__device__ int    g_esrc[N_EDGES];             // src ids grouped by dst (overwritten)
__device__ int    g_scan_pack[SCAN_BLOCKS];    // lookback state (zeroed by k_scatter)
__device__ int    g_hg[N_GRAPHS * F];          // per-graph max bits (zeroed by k_mlp)

// ---------------- helpers ----------------
__device__ __forceinline__ unsigned long long pack2(float x) {
    unsigned long long r;
    asm("mov.b64 %0, {%1, %1};" : "=l"(r) : "f"(x));
    return r;
}
__device__ __forceinline__ void ffma2(unsigned long long& d,
                                      unsigned long long a,
                                      unsigned long long b) {
    asm("fma.rn.f32x2 %0, %1, %2, %0;" : "+l"(d) : "l"(a), "l"(b));
}
__device__ __forceinline__ void unpack2(unsigned long long v, float& lo, float& hi) {
    asm("mov.b64 {%0, %1}, %2;" : "=f"(lo), "=f"(hi) : "l"(v));
}
__device__ __forceinline__ int ld_relaxed(const int* p) {
    int v;
    asm volatile("ld.relaxed.gpu.global.b32 %0, [%1];" : "=r"(v) : "l"(p));
    return v;
}

// ---------------- [0] degree histogram (int4 reads, 4 atomics/thread) ----------------
__global__ void k_hist(const int4* __restrict__ dst4) {
    int t = blockIdx.x * blockDim.x + threadIdx.x;
    if (t < N_EDGES / 4) {
        int4 d = dst4[t];
        atomicAdd(&g_cnt[d.x], 1);
        atomicAdd(&g_cnt[d.y], 1);
        atomicAdd(&g_cnt[d.z], 1);
        atomicAdd(&g_cnt[d.w], 1);
    }
}

// ---------------- [1] single-pass exclusive scan (decoupled lookback) ----------------
__global__ void __launch_bounds__(1024) k_scan() {
    __shared__ int s[1024];
    __shared__ int s_exc;
    int tid = threadIdx.x;
    int b = blockIdx.x;
    int i = b * 1024 + tid;
    int v = (i < N_NODES) ? g_cnt[i] : 0;
    s[tid] = v;
    __syncthreads();
#pragma unroll
    for (int d = 1; d < 1024; d <<= 1) {
        int t = (tid >= d) ? s[tid - d] : 0;
        __syncthreads();
        s[tid] += t;
        __syncthreads();
    }
    int total = s[1023];

    if (tid == 0) {
        if (b == 0) {
            atomicExch(&g_scan_pack[0], (total << 2) | 2);
            s_exc = 0;
        } else {
            atomicExch(&g_scan_pack[b], (total << 2) | 1);
            int running = 0;
            int p = b - 1;
            while (true) {
                int w;
                do { w = ld_relaxed(&g_scan_pack[p]); } while ((w & 3) == 0);
                running += (w >> 2);
                if ((w & 3) == 2) break;
                p--;
            }
            atomicExch(&g_scan_pack[b], ((running + total) << 2) | 2);
            s_exc = running;
        }
    }
    __syncthreads();
    if (i < N_NODES) {
        int off = s[tid] - v + s_exc;
        g_off[i] = off;
        g_cursor[i] = off;
    }
}

// ---------------- [2] scatter + cleanup of scan flags ----------------
__global__ void k_scatter(const int* __restrict__ src, const int* __restrict__ dst) {
    int e = blockIdx.x * blockDim.x + threadIdx.x;
    if (e < N_EDGES) {
        int p = atomicAdd(&g_cursor[dst[e]], 1);
        g_esrc[p] = src[e];
    }
    if (blockIdx.x == 0 && threadIdx.x < SCAN_BLOCKS)
        g_scan_pack[threadIdx.x] = 0;            // ready for next replay's k_scan
}

// ---------------- [3] gather-aggregate (PROFILED SLOT) + cnt cleanup ----------------
// 16 threads per node; thread q owns float4 column q.
__global__ void __launch_bounds__(256) k_gather(const float4* __restrict__ feats4) {
    int t = blockIdx.x * 256 + threadIdx.x;
    int node = t >> 4;
    int q = t & 15;
    if (node >= N_NODES) return;
    int start = g_off[node];
    int n = g_cnt[node];
    if (q == 0) g_cnt[node] = 0;                 // self-clean for next replay
    const int* ep = &g_esrc[start];

    float4 a0 = make_float4(0.f, 0.f, 0.f, 0.f);
    float4 a1 = a0, a2 = a0, a3 = a0;
    int i = 0;
    for (; i + 4 <= n; i += 4) {
        int s0 = ep[i], s1 = ep[i + 1], s2 = ep[i + 2], s3 = ep[i + 3];
        float4 v0 = feats4[(long long)s0 * 16 + q];
        float4 v1 = feats4[(long long)s1 * 16 + q];
        float4 v2 = feats4[(long long)s2 * 16 + q];
        float4 v3 = feats4[(long long)s3 * 16 + q];
        a0.x += v0.x; a0.y += v0.y; a0.z += v0.z; a0.w += v0.w;
        a1.x += v1.x; a1.y += v1.y; a1.z += v1.z; a1.w += v1.w;
        a2.x += v2.x; a2.y += v2.y; a2.z += v2.z; a2.w += v2.w;
        a3.x += v3.x; a3.y += v3.y; a3.z += v3.z; a3.w += v3.w;
    }
    for (; i < n; i++) {
        int s = ep[i];
        float4 v = feats4[(long long)s * 16 + q];
        a0.x += v.x; a0.y += v.y; a0.z += v.z; a0.w += v.w;
    }
    float4 acc;
    acc.x = (a0.x + a1.x) + (a2.x + a3.x);
    acc.y = (a0.y + a1.y) + (a2.y + a3.y);
    acc.z = (a0.z + a1.z) + (a2.z + a3.z);
    acc.w = (a0.w + a1.w) + (a2.w + a3.w);
    float inv = 1.0f / (float)max(n, 1);
    acc.x *= inv; acc.y *= inv; acc.z *= inv; acc.w *= inv;
    g_agg4[(long long)node * 16 + q] = acc;      // stores the MEAN
}

// ---------------- [4] node update: 2 threads/node, 32 outputs each ----------------
__global__ void __launch_bounds__(256)
k_node(const float4* __restrict__ feats4,
       const float*  __restrict__ Wself,
       const float*  __restrict__ Wneigh,
       const float*  __restrict__ bneigh,
       const int*    __restrict__ gids) {
    __shared__ float sWs[F * F];
    __shared__ float sWn[F * F];
    for (int i = threadIdx.x; i < F * F; i += 256) {
        sWs[i] = Wself[i];
        sWn[i] = Wneigh[i];
    }
    __syncthreads();

    int t = blockIdx.x * 256 + threadIdx.x;
    int node = t >> 1;
    int half = t & 1;                 // outputs [half*32, half*32+32)
    if (node >= N_NODES) return;

    unsigned long long h2[16];        // 32 packed fp32 outputs
#pragma unroll
    for (int o = 0; o < 16; o++) h2[o] = 0ULL;

#pragma unroll
    for (int kk = 0; kk < 16; kk++) {
        float4 fs = feats4[(long long)node * 16 + kk];
        float4 fm = g_agg4[(long long)node * 16 + kk];   // already the mean
        float xs[4] = {fs.x, fs.y, fs.z, fs.w};
        float xm[4] = {fm.x, fm.y, fm.z, fm.w};
#pragma unroll
        for (int j = 0; j < 4; j++) {
            int k = kk * 4 + j;
            unsigned long long xs2 = pack2(xs[j]);
            unsigned long long xm2 = pack2(xm[j]);
            const ulonglong2* wsr = (const ulonglong2*)&sWs[k * F + half * 32];
            const ulonglong2* wnr = (const ulonglong2*)&sWn[k * F + half * 32];
#pragma unroll
            for (int o4 = 0; o4 < 8; o4++) {
                ulonglong2 ws = wsr[o4];
                ulonglong2 wn = wnr[o4];
                ffma2(h2[o4 * 2 + 0], xs2, ws.x);
                ffma2(h2[o4 * 2 + 0], xm2, wn.x);
                ffma2(h2[o4 * 2 + 1], xs2, ws.y);
                ffma2(h2[o4 * 2 + 1], xm2, wn.y);
            }
        }
    }

    int g = gids[node];
    int obase = half * 32;
#pragma unroll
    for (int o2 = 0; o2 < 16; o2++) {
        float lo, hi;
        unpack2(h2[o2], lo, hi);
        int o = obase + o2 * 2;
        float v0 = fmaxf(lo + bneigh[o + 0], 0.0f);   // relu; >= 0
        float v1 = fmaxf(hi + bneigh[o + 1], 0.0f);
        atomicMax(&g_hg[g * F + o + 0], __float_as_int(v0));
        atomicMax(&g_hg[g * F + o + 1], __float_as_int(v1));
    }
}

// ---------------- [5] MLP head: one warp per graph + g_hg cleanup ----------------
__global__ void __launch_bounds__(128)
k_mlp(const float* __restrict__ W1, const float* __restrict__ b1,
      const float* __restrict__ g1, const float* __restrict__ be1,
      const float* __restrict__ rm1, const float* __restrict__ rv1,
      const float* __restrict__ W2, const float* __restrict__ b2,
      const float* __restrict__ g2, const float* __restrict__ be2,
      const float* __restrict__ rm2, const float* __restrict__ rv2,
      const float* __restrict__ W3, const float* __restrict__ b3,
      float* __restrict__ out) {
    __shared__ float sh[4][F];
    __shared__ float sy[4][128];

    int w = threadIdx.x >> 5;
    int lane = threadIdx.x & 31;
    int g = blockIdx.x * 4 + w;

    sh[w][lane]      = __int_as_float(g_hg[g * F + lane]);
    sh[w][lane + 32] = __int_as_float(g_hg[g * F + lane + 32]);
    g_hg[g * F + lane]      = 0;    // self-clean for next replay's atomicMax
    g_hg[g * F + lane + 32] = 0;
    __syncwarp();

    // layer 1: 64 -> 128
    float a0 = b1[lane], a1 = b1[lane + 32], a2 = b1[lane + 64], a3 = b1[lane + 96];
#pragma unroll 8
    for (int k = 0; k < F; k++) {
        float xv = sh[w][k];
        const float* wr = &W1[k * 128 + lane];
        a0 = fmaf(xv, wr[0],  a0);
        a1 = fmaf(xv, wr[32], a1);
        a2 = fmaf(xv, wr[64], a2);
        a3 = fmaf(xv, wr[96], a3);
    }
    {
        float acc[4] = {a0, a1, a2, a3};
#pragma unroll
        for (int m = 0; m < 4; m++) {
            int j = lane + 32 * m;
            float a = fmaxf(acc[m], 0.0f);
            a = (a - rm1[j]) * rsqrtf(rv1[j] + BN_EPS) * g1[j] + be1[j];
            sy[w][j] = a;
        }
    }
    __syncwarp();

    // layer 2: 128 -> 64
    float c0 = b2[lane], c1 = b2[lane + 32];
#pragma unroll 8
    for (int k = 0; k < 128; k++) {
        float yv = sy[w][k];
        const float* wr = &W2[k * F + lane];
        c0 = fmaf(yv, wr[0],  c0);
        c1 = fmaf(yv, wr[32], c1);
    }
    float p;
    {
        int j0 = lane, j1 = lane + 32;
        float x0 = fmaxf(c0, 0.0f);
        x0 = (x0 - rm2[j0]) * rsqrtf(rv2[j0] + BN_EPS) * g2[j0] + be2[j0];
        float x1 = fmaxf(c1, 0.0f);
        x1 = (x1 - rm2[j1]) * rsqrtf(rv2[j1] + BN_EPS) * g2[j1] + be2[j1];
        p = x0 * W3[j0] + x1 * W3[j1];
    }
#pragma unroll
    for (int off = 16; off > 0; off >>= 1)
        p += __shfl_down_sync(0xFFFFFFFFu, p, off);
    if (lane == 0) out[g] = p + b3[0];
}

// ---------------- launcher ----------------
extern "C" void kernel_launch(void* const* d_in, const int* in_sizes, int n_in,
                              void* d_out, int out_size) {
    const float4* feats4 = (const float4*)d_in[0];
    const int*    src    = (const int*)d_in[1];
    const int*    dst    = (const int*)d_in[2];
    const int*    gids   = (const int*)d_in[3];
    const float*  Wself  = (const float*)d_in[4];
    const float*  Wneigh = (const float*)d_in[5];
    const float*  bneigh = (const float*)d_in[6];
    const float*  W1  = (const float*)d_in[7];
    const float*  b1  = (const float*)d_in[8];
    const float*  g1  = (const float*)d_in[9];
    const float*  be1 = (const float*)d_in[10];
    const float*  rm1 = (const float*)d_in[11];
    const float*  rv1 = (const float*)d_in[12];
    const float*  W2  = (const float*)d_in[13];
    const float*  b2  = (const float*)d_in[14];
    const float*  g2  = (const float*)d_in[15];
    const float*  be2 = (const float*)d_in[16];
    const float*  rm2 = (const float*)d_in[17];
    const float*  rv2 = (const float*)d_in[18];
    const float*  W3  = (const float*)d_in[19];
    const float*  b3  = (const float*)d_in[20];
    float* out = (float*)d_out;

    k_hist<<<(N_EDGES / 4 + 255) / 256, 256>>>((const int4*)dst);
    k_scan<<<SCAN_BLOCKS, 1024>>>();
    k_scatter<<<(N_EDGES + 255) / 256, 256>>>(src, dst);
    k_gather<<<(N_NODES * 16 + 255) / 256, 256>>>(feats4);        // profiled slot 3
    k_node<<<(N_NODES * 2 + 255) / 256, 256>>>(feats4, Wself, Wneigh, bneigh, gids);
    k_mlp<<<N_GRAPHS / 4, 128>>>(W1, b1, g1, be1, rm1, rv1,
                                 W2, b2, g2, be2, rm2, rv2,
                                 W3, b3, out);
}

// round 11
// speedup vs baseline: 1.5999x; 1.5999x over previous
#include <cuda_runtime.h>
#include <cstdint>

#define N_NODES  100000
#define N_EDGES  1200000
#define N_GRAPHS 1024
#define F        64
#define BN_EPS   1e-5f
#define SCAN_BLOCKS 98          // ceil(100000/1024)

// ---------------- device scratch (no allocations allowed) ----------------
// Self-cleaning invariant: g_cnt, g_scan_pack, g_hg are ALL-ZERO before and
// after every kernel_launch execution (static zero-init covers the first).
__device__ float4 g_agg4[N_NODES * (F / 4)];   // neighbor MEANS (fully overwritten)
__device__ int    g_cnt[N_NODES];              // in-degree   (zeroed by k_gather)
__device__ int    g_off[N_NODES];              // CSR offsets (fully overwritten)
__device__ int    g_cursor[N_NODES];           // scatter cursors (fully overwritten)
__device__ int    g_esrc[N_EDGES];             // src ids grouped by dst (overwritten)
__device__ int    g_scan_pack[SCAN_BLOCKS];    // lookback state (zeroed by k_scatter)
__device__ int    g_hg[N_GRAPHS * F];          // per-graph max bits (zeroed by k_mlp)

// ---------------- helpers ----------------
__device__ __forceinline__ unsigned long long pack2(float x) {
    unsigned long long r;
    asm("mov.b64 %0, {%1, %1};" : "=l"(r) : "f"(x));
    return r;
}
__device__ __forceinline__ void ffma2(unsigned long long& d,
                                      unsigned long long a,
                                      unsigned long long b) {
    asm("fma.rn.f32x2 %0, %1, %2, %0;" : "+l"(d) : "l"(a), "l"(b));
}
__device__ __forceinline__ void add2(unsigned long long& d, unsigned long long a) {
    asm("add.rn.f32x2 %0, %0, %1;" : "+l"(d) : "l"(a));
}
__device__ __forceinline__ void mul2(unsigned long long& d, unsigned long long a) {
    asm("mul.rn.f32x2 %0, %0, %1;" : "+l"(d) : "l"(a));
}
__device__ __forceinline__ void unpack2(unsigned long long v, float& lo, float& hi) {
    asm("mov.b64 {%0, %1}, %2;" : "=f"(lo), "=f"(hi) : "l"(v));
}
__device__ __forceinline__ int ld_relaxed(const int* p) {
    int v;
    asm volatile("ld.relaxed.gpu.global.b32 %0, [%1];" : "=r"(v) : "l"(p));
    return v;
}

// ---------------- [0] degree histogram (scalar, proven) ----------------
__global__ void k_hist(const int* __restrict__ dst) {
    int e = blockIdx.x * blockDim.x + threadIdx.x;
    if (e < N_EDGES) atomicAdd(&g_cnt[dst[e]], 1);
}

// ---------------- [1] single-pass exclusive scan (decoupled lookback) ----------------
__global__ void __launch_bounds__(1024) k_scan() {
    __shared__ int s[1024];
    __shared__ int s_exc;
    int tid = threadIdx.x;
    int b = blockIdx.x;
    int i = b * 1024 + tid;
    int v = (i < N_NODES) ? g_cnt[i] : 0;
    s[tid] = v;
    __syncthreads();
#pragma unroll
    for (int d = 1; d < 1024; d <<= 1) {
        int t = (tid >= d) ? s[tid - d] : 0;
        __syncthreads();
        s[tid] += t;
        __syncthreads();
    }
    int total = s[1023];

    if (tid == 0) {
        if (b == 0) {
            atomicExch(&g_scan_pack[0], (total << 2) | 2);
            s_exc = 0;
        } else {
            atomicExch(&g_scan_pack[b], (total << 2) | 1);
            int running = 0;
            int p = b - 1;
            while (true) {
                int w;
                do { w = ld_relaxed(&g_scan_pack[p]); } while ((w & 3) == 0);
                running += (w >> 2);
                if ((w & 3) == 2) break;
                p--;
            }
            atomicExch(&g_scan_pack[b], ((running + total) << 2) | 2);
            s_exc = running;
        }
    }
    __syncthreads();
    if (i < N_NODES) {
        int off = s[tid] - v + s_exc;
        g_off[i] = off;
        g_cursor[i] = off;
    }
}

// ---------------- [2] scatter + cleanup of scan flags ----------------
__global__ void k_scatter(const int* __restrict__ src, const int* __restrict__ dst) {
    int e = blockIdx.x * blockDim.x + threadIdx.x;
    if (e < N_EDGES) {
        int p = atomicAdd(&g_cursor[dst[e]], 1);
        g_esrc[p] = src[e];
    }
    if (blockIdx.x == 0 && threadIdx.x < SCAN_BLOCKS)
        g_scan_pack[threadIdx.x] = 0;            // ready for next replay's k_scan
}

// ---------------- [3] gather-aggregate (PROFILED SLOT) + cnt cleanup ----------------
// 16 threads per node; thread q owns one 16B column. Unroll-8: 8 independent
// LDG.128 in flight per thread (2KB/warp), packed f32x2 accumulation.
__global__ void __launch_bounds__(256) k_gather(const float4* __restrict__ feats4) {
    int t = blockIdx.x * 256 + threadIdx.x;
    int node = t >> 4;
    unsigned q = t & 15;
    if (node >= N_NODES) return;
    int start = g_off[node];
    int n = g_cnt[node];
    if (q == 0) g_cnt[node] = 0;                 // self-clean for next replay
    const int* ep = &g_esrc[start];
    const ulonglong2* f2 = (const ulonglong2*)feats4;

    ulonglong2 a0, a1, a2, a3;
    a0.x = a0.y = a1.x = a1.y = a2.x = a2.y = a3.x = a3.y = 0ULL;  // +0.0f pairs

    int i = 0;
    for (; i + 8 <= n; i += 8) {
        unsigned s0 = (unsigned)ep[i]     * 16u + q;
        unsigned s1 = (unsigned)ep[i + 1] * 16u + q;
        unsigned s2 = (unsigned)ep[i + 2] * 16u + q;
        unsigned s3 = (unsigned)ep[i + 3] * 16u + q;
        unsigned s4 = (unsigned)ep[i + 4] * 16u + q;
        unsigned s5 = (unsigned)ep[i + 5] * 16u + q;
        unsigned s6 = (unsigned)ep[i + 6] * 16u + q;
        unsigned s7 = (unsigned)ep[i + 7] * 16u + q;
        ulonglong2 v0 = f2[s0];
        ulonglong2 v1 = f2[s1];
        ulonglong2 v2 = f2[s2];
        ulonglong2 v3 = f2[s3];
        ulonglong2 v4 = f2[s4];
        ulonglong2 v5 = f2[s5];
        ulonglong2 v6 = f2[s6];
        ulonglong2 v7 = f2[s7];
        add2(a0.x, v0.x); add2(a0.y, v0.y);
        add2(a1.x, v1.x); add2(a1.y, v1.y);
        add2(a2.x, v2.x); add2(a2.y, v2.y);
        add2(a3.x, v3.x); add2(a3.y, v3.y);
        add2(a0.x, v4.x); add2(a0.y, v4.y);
        add2(a1.x, v5.x); add2(a1.y, v5.y);
        add2(a2.x, v6.x); add2(a2.y, v6.y);
        add2(a3.x, v7.x); add2(a3.y, v7.y);
    }
    for (; i + 2 <= n; i += 2) {
        unsigned s0 = (unsigned)ep[i]     * 16u + q;
        unsigned s1 = (unsigned)ep[i + 1] * 16u + q;
        ulonglong2 v0 = f2[s0];
        ulonglong2 v1 = f2[s1];
        add2(a0.x, v0.x); add2(a0.y, v0.y);
        add2(a1.x, v1.x); add2(a1.y, v1.y);
    }
    if (i < n) {
        unsigned s0 = (unsigned)ep[i] * 16u + q;
        ulonglong2 v0 = f2[s0];
        add2(a0.x, v0.x); add2(a0.y, v0.y);
    }

    add2(a0.x, a1.x); add2(a0.y, a1.y);
    add2(a2.x, a3.x); add2(a2.y, a3.y);
    add2(a0.x, a2.x); add2(a0.y, a2.y);

    unsigned long long inv2 = pack2(1.0f / (float)max(n, 1));
    mul2(a0.x, inv2);
    mul2(a0.y, inv2);
    ((ulonglong2*)g_agg4)[(unsigned)node * 16u + q] = a0;   // stores the MEAN
}

// ---------------- [4] node update: 1 thread/node (proven R5 form) ----------------
__global__ void __launch_bounds__(256)
k_node(const float4* __restrict__ feats4,
       const float*  __restrict__ Wself,
       const float*  __restrict__ Wneigh,
       const float*  __restrict__ bneigh,
       const int*    __restrict__ gids) {
    __shared__ float sWs[F * F];
    __shared__ float sWn[F * F];
    for (int i = threadIdx.x; i < F * F; i += 256) {
        sWs[i] = Wself[i];
        sWn[i] = Wneigh[i];
    }
    __syncthreads();

    int node = blockIdx.x * 256 + threadIdx.x;
    if (node >= N_NODES) return;

    unsigned long long h2[F / 2];
#pragma unroll
    for (int o = 0; o < F / 2; o++) h2[o] = 0ULL;

#pragma unroll
    for (int kk = 0; kk < 16; kk++) {
        float4 fs = feats4[(long long)node * 16 + kk];
        float4 fm = g_agg4[(long long)node * 16 + kk];   // already the mean
        float xs[4] = {fs.x, fs.y, fs.z, fs.w};
        float xm[4] = {fm.x, fm.y, fm.z, fm.w};
#pragma unroll
        for (int j = 0; j < 4; j++) {
            int k = kk * 4 + j;
            unsigned long long xs2 = pack2(xs[j]);
            unsigned long long xm2 = pack2(xm[j]);
            const ulonglong2* wsr = (const ulonglong2*)&sWs[k * F];
            const ulonglong2* wnr = (const ulonglong2*)&sWn[k * F];
#pragma unroll
            for (int o4 = 0; o4 < 16; o4++) {
                ulonglong2 ws = wsr[o4];   // LDS.128, warp-broadcast
                ulonglong2 wn = wnr[o4];
                ffma2(h2[o4 * 2 + 0], xs2, ws.x);
                ffma2(h2[o4 * 2 + 0], xm2, wn.x);
                ffma2(h2[o4 * 2 + 1], xs2, ws.y);
                ffma2(h2[o4 * 2 + 1], xm2, wn.y);
            }
        }
    }

    int g = gids[node];
#pragma unroll
    for (int o2 = 0; o2 < F / 2; o2++) {
        float lo, hi;
        unpack2(h2[o2], lo, hi);
        float v0 = fmaxf(lo + bneigh[o2 * 2 + 0], 0.0f);   // relu; >= 0
        float v1 = fmaxf(hi + bneigh[o2 * 2 + 1], 0.0f);
        atomicMax(&g_hg[g * F + o2 * 2 + 0], __float_as_int(v0));
        atomicMax(&g_hg[g * F + o2 * 2 + 1], __float_as_int(v1));
    }
}

// ---------------- [5] MLP head: one warp per graph + g_hg cleanup ----------------
__global__ void __launch_bounds__(128)
k_mlp(const float* __restrict__ W1, const float* __restrict__ b1,
      const float* __restrict__ g1, const float* __restrict__ be1,
      const float* __restrict__ rm1, const float* __restrict__ rv1,
      const float* __restrict__ W2, const float* __restrict__ b2,
      const float* __restrict__ g2, const float* __restrict__ be2,
      const float* __restrict__ rm2, const float* __restrict__ rv2,
      const float* __restrict__ W3, const float* __restrict__ b3,
      float* __restrict__ out) {
    __shared__ float sh[4][F];
    __shared__ float sy[4][128];

    int w = threadIdx.x >> 5;
    int lane = threadIdx.x & 31;
    int g = blockIdx.x * 4 + w;

    sh[w][lane]      = __int_as_float(g_hg[g * F + lane]);
    sh[w][lane + 32] = __int_as_float(g_hg[g * F + lane + 32]);
    g_hg[g * F + lane]      = 0;    // self-clean for next replay's atomicMax
    g_hg[g * F + lane + 32] = 0;
    __syncwarp();

    // layer 1: 64 -> 128
    float a0 = b1[lane], a1 = b1[lane + 32], a2 = b1[lane + 64], a3 = b1[lane + 96];
#pragma unroll 8
    for (int k = 0; k < F; k++) {
        float xv = sh[w][k];
        const float* wr = &W1[k * 128 + lane];
        a0 = fmaf(xv, wr[0],  a0);
        a1 = fmaf(xv, wr[32], a1);
        a2 = fmaf(xv, wr[64], a2);
        a3 = fmaf(xv, wr[96], a3);
    }
    {
        float acc[4] = {a0, a1, a2, a3};
#pragma unroll
        for (int m = 0; m < 4; m++) {
            int j = lane + 32 * m;
            float a = fmaxf(acc[m], 0.0f);
            a = (a - rm1[j]) * rsqrtf(rv1[j] + BN_EPS) * g1[j] + be1[j];
            sy[w][j] = a;
        }
    }
    __syncwarp();

    // layer 2: 128 -> 64
    float c0 = b2[lane], c1 = b2[lane + 32];
#pragma unroll 8
    for (int k = 0; k < 128; k++) {
        float yv = sy[w][k];
        const float* wr = &W2[k * F + lane];
        c0 = fmaf(yv, wr[0],  c0);
        c1 = fmaf(yv, wr[32], c1);
    }
    float p;
    {
        int j0 = lane, j1 = lane + 32;
        float x0 = fmaxf(c0, 0.0f);
        x0 = (x0 - rm2[j0]) * rsqrtf(rv2[j0] + BN_EPS) * g2[j0] + be2[j0];
        float x1 = fmaxf(c1, 0.0f);
        x1 = (x1 - rm2[j1]) * rsqrtf(rv2[j1] + BN_EPS) * g2[j1] + be2[j1];
        p = x0 * W3[j0] + x1 * W3[j1];
    }
#pragma unroll
    for (int off = 16; off > 0; off >>= 1)
        p += __shfl_down_sync(0xFFFFFFFFu, p, off);
    if (lane == 0) out[g] = p + b3[0];
}

// ---------------- launcher ----------------
extern "C" void kernel_launch(void* const* d_in, const int* in_sizes, int n_in,
                              void* d_out, int out_size) {
    const float4* feats4 = (const float4*)d_in[0];
    const int*    src    = (const int*)d_in[1];
    const int*    dst    = (const int*)d_in[2];
    const int*    gids   = (const int*)d_in[3];
    const float*  Wself  = (const float*)d_in[4];
    const float*  Wneigh = (const float*)d_in[5];
    const float*  bneigh = (const float*)d_in[6];
    const float*  W1  = (const float*)d_in[7];
    const float*  b1  = (const float*)d_in[8];
    const float*  g1  = (const float*)d_in[9];
    const float*  be1 = (const float*)d_in[10];
    const float*  rm1 = (const float*)d_in[11];
    const float*  rv1 = (const float*)d_in[12];
    const float*  W2  = (const float*)d_in[13];
    const float*  b2  = (const float*)d_in[14];
    const float*  g2  = (const float*)d_in[15];
    const float*  be2 = (const float*)d_in[16];
    const float*  rm2 = (const float*)d_in[17];
    const float*  rv2 = (const float*)d_in[18];
    const float*  W3  = (const float*)d_in[19];
    const float*  b3  = (const float*)d_in[20];
    float* out = (float*)d_out;

    k_hist<<<(N_EDGES + 255) / 256, 256>>>(dst);
    k_scan<<<SCAN_BLOCKS, 1024>>>();
    k_scatter<<<(N_EDGES + 255) / 256, 256>>>(src, dst);
    k_gather<<<(N_NODES * 16 + 255) / 256, 256>>>(feats4);        // profiled slot 3
    k_node<<<(N_NODES + 255) / 256, 256>>>(feats4, Wself, Wneigh, bneigh, gids);
    k_mlp<<<N_GRAPHS / 4, 128>>>(W1, b1, g1, be1, rm1, rv1,
                                 W2, b2, g2, be2, rm2, rv2,
                                 W3, b3, out);
}

// round 12
// speedup vs baseline: 1.9234x; 1.2022x over previous
#include <cuda_runtime.h>
#include <cuda_fp16.h>
#include <cstdint>

#define N_NODES  100000
#define N_EDGES  1200000
#define N_GRAPHS 1024
#define F        64
#define BN_EPS   1e-5f
#define SCAN_BLOCKS 98          // ceil(100000/1024)

// ---------------- device scratch (no allocations allowed) ----------------
__device__ float4 g_agg4[N_NODES * (F / 4)];   // neighbor MEANS (fully overwritten)
__device__ uint4  g_featsh4[N_NODES * F / 8];  // fp16 feats, 128B/row (12.8MB)
__device__ int    g_cnt[N_NODES];              // in-degree
__device__ int    g_off[N_NODES];              // CSR offsets
__device__ int    g_cursor[N_NODES];           // scatter cursors
__device__ int    g_esrc[N_EDGES];             // src ids grouped by dst
__device__ int    g_scan_pack[SCAN_BLOCKS];    // lookback state
__device__ int    g_hg[N_GRAPHS * F];          // per-graph max, float bits as int

// ---------------- helpers ----------------
__device__ __forceinline__ unsigned long long pack2(float x) {
    unsigned long long r;
    asm("mov.b64 %0, {%1, %1};" : "=l"(r) : "f"(x));
    return r;
}
__device__ __forceinline__ void ffma2(unsigned long long& d,
                                      unsigned long long a,
                                      unsigned long long b) {
    asm("fma.rn.f32x2 %0, %1, %2, %0;" : "+l"(d) : "l"(a), "l"(b));
}
__device__ __forceinline__ void unpack2(unsigned long long v, float& lo, float& hi) {
    asm("mov.b64 {%0, %1}, %2;" : "=f"(lo), "=f"(hi) : "l"(v));
}
__device__ __forceinline__ int ld_relaxed(const int* p) {
    int v;
    asm volatile("ld.relaxed.gpu.global.b32 %0, [%1];" : "=r"(v) : "l"(p));
    return v;
}
__device__ __forceinline__ void acc_h2(float2& a, unsigned u) {
    __half2 h = *(__half2*)&u;
    float2 f = __half22float2(h);
    a.x += f.x; a.y += f.y;
}

// ---------------- [0] init: zero atomic targets (L2-warm!) + feats->fp16 ----------------
__global__ void k_init(const float2* __restrict__ feats2) {
    int i = blockIdx.x * blockDim.x + threadIdx.x;
    int stride = gridDim.x * blockDim.x;
    __half2* fh2 = (__half2*)g_featsh4;
    for (int t = i; t < N_NODES * F / 2; t += stride)
        fh2[t] = __float22half2_rn(feats2[t]);
    int4 zi = make_int4(0, 0, 0, 0);
    int4* cnt4 = (int4*)g_cnt;                         // 100000 % 4 == 0
    for (int t = i; t < N_NODES / 4; t += stride) cnt4[t] = zi;
    int4* hg4 = (int4*)g_hg;
    for (int t = i; t < N_GRAPHS * F / 4; t += stride) hg4[t] = zi;  // 0 == +0.0f bits
    if (i < SCAN_BLOCKS) g_scan_pack[i] = 0;
}

// ---------------- [1] degree histogram ----------------
__global__ void k_hist(const int* __restrict__ dst) {
    int e = blockIdx.x * blockDim.x + threadIdx.x;
    if (e < N_EDGES) atomicAdd(&g_cnt[dst[e]], 1);
}

// ---------------- [2] single-pass exclusive scan (decoupled lookback) ----------------
__global__ void __launch_bounds__(1024) k_scan() {
    __shared__ int s[1024];
    __shared__ int s_exc;
    int tid = threadIdx.x;
    int b = blockIdx.x;
    int i = b * 1024 + tid;
    int v = (i < N_NODES) ? g_cnt[i] : 0;
    s[tid] = v;
    __syncthreads();
#pragma unroll
    for (int d = 1; d < 1024; d <<= 1) {
        int t = (tid >= d) ? s[tid - d] : 0;
        __syncthreads();
        s[tid] += t;
        __syncthreads();
    }
    int total = s[1023];

    if (tid == 0) {
        if (b == 0) {
            atomicExch(&g_scan_pack[0], (total << 2) | 2);
            s_exc = 0;
        } else {
            atomicExch(&g_scan_pack[b], (total << 2) | 1);
            int running = 0;
            int p = b - 1;
            while (true) {
                int w;
                do { w = ld_relaxed(&g_scan_pack[p]); } while ((w & 3) == 0);
                running += (w >> 2);
                if ((w & 3) == 2) break;
                p--;
            }
            atomicExch(&g_scan_pack[b], ((running + total) << 2) | 2);
            s_exc = running;
        }
    }
    __syncthreads();
    if (i < N_NODES) {
        int off = s[tid] - v + s_exc;
        g_off[i] = off;
        g_cursor[i] = off;
    }
}

// ---------------- [3] scatter: bucket src ids by dst ----------------
__global__ void k_scatter(const int* __restrict__ src, const int* __restrict__ dst) {
    int e = blockIdx.x * blockDim.x + threadIdx.x;
    if (e < N_EDGES) {
        int p = atomicAdd(&g_cursor[dst[e]], 1);
        g_esrc[p] = src[e];
    }
}

// ---------------- [4] gather-aggregate over fp16 rows (1 line per edge-row) ----------------
// 8 threads per node; thread q owns 16B = 8 halves. fp32 accumulation.
__global__ void __launch_bounds__(256) k_gather() {
    int t = blockIdx.x * 256 + threadIdx.x;
    int node = t >> 3;
    unsigned q = t & 7;
    if (node >= N_NODES) return;
    int start = g_off[node];
    int n = g_cnt[node];
    const int* ep = &g_esrc[start];

    float2 A0 = make_float2(0.f, 0.f), A1 = A0, A2 = A0, A3 = A0;
    float2 B0 = A0, B1 = A0, B2 = A0, B3 = A0;

    int i = 0;
    for (; i + 4 <= n; i += 4) {
        unsigned s0 = (unsigned)ep[i]     * 8u + q;
        unsigned s1 = (unsigned)ep[i + 1] * 8u + q;
        unsigned s2 = (unsigned)ep[i + 2] * 8u + q;
        unsigned s3 = (unsigned)ep[i + 3] * 8u + q;
        uint4 v0 = g_featsh4[s0];
        uint4 v1 = g_featsh4[s1];
        uint4 v2 = g_featsh4[s2];
        uint4 v3 = g_featsh4[s3];
        acc_h2(A0, v0.x); acc_h2(A1, v0.y); acc_h2(A2, v0.z); acc_h2(A3, v0.w);
        acc_h2(B0, v1.x); acc_h2(B1, v1.y); acc_h2(B2, v1.z); acc_h2(B3, v1.w);
        acc_h2(A0, v2.x); acc_h2(A1, v2.y); acc_h2(A2, v2.z); acc_h2(A3, v2.w);
        acc_h2(B0, v3.x); acc_h2(B1, v3.y); acc_h2(B2, v3.z); acc_h2(B3, v3.w);
    }
    for (; i < n; i++) {
        unsigned s0 = (unsigned)ep[i] * 8u + q;
        uint4 v0 = g_featsh4[s0];
        acc_h2(A0, v0.x); acc_h2(A1, v0.y); acc_h2(A2, v0.z); acc_h2(A3, v0.w);
    }
    A0.x += B0.x; A0.y += B0.y;
    A1.x += B1.x; A1.y += B1.y;
    A2.x += B2.x; A2.y += B2.y;
    A3.x += B3.x; A3.y += B3.y;

    float inv = 1.0f / (float)max(n, 1);
    float4 st0 = make_float4(A0.x * inv, A0.y * inv, A1.x * inv, A1.y * inv);
    float4 st1 = make_float4(A2.x * inv, A2.y * inv, A3.x * inv, A3.y * inv);
    g_agg4[(unsigned)node * 16u + 2u * q + 0u] = st0;   // stores the MEAN
    g_agg4[(unsigned)node * 16u + 2u * q + 1u] = st1;
}

// ---------------- [5] node update: 1 thread/node (proven R5 form) ----------------
__global__ void __launch_bounds__(256)
k_node(const float4* __restrict__ feats4,
       const float*  __restrict__ Wself,
       const float*  __restrict__ Wneigh,
       const float*  __restrict__ bneigh,
       const int*    __restrict__ gids) {
    __shared__ float sWs[F * F];
    __shared__ float sWn[F * F];
    for (int i = threadIdx.x; i < F * F; i += 256) {
        sWs[i] = Wself[i];
        sWn[i] = Wneigh[i];
    }
    __syncthreads();

    int node = blockIdx.x * 256 + threadIdx.x;
    if (node >= N_NODES) return;

    unsigned long long h2[F / 2];
#pragma unroll
    for (int o = 0; o < F / 2; o++) h2[o] = 0ULL;

#pragma unroll
    for (int kk = 0; kk < 16; kk++) {
        float4 fs = feats4[(long long)node * 16 + kk];
        float4 fm = g_agg4[(long long)node * 16 + kk];   // already the mean
        float xs[4] = {fs.x, fs.y, fs.z, fs.w};
        float xm[4] = {fm.x, fm.y, fm.z, fm.w};
#pragma unroll
        for (int j = 0; j < 4; j++) {
            int k = kk * 4 + j;
            unsigned long long xs2 = pack2(xs[j]);
            unsigned long long xm2 = pack2(xm[j]);
            const ulonglong2* wsr = (const ulonglong2*)&sWs[k * F];
            const ulonglong2* wnr = (const ulonglong2*)&sWn[k * F];
#pragma unroll
            for (int o4 = 0; o4 < 16; o4++) {
                ulonglong2 ws = wsr[o4];   // LDS.128, warp-broadcast
                ulonglong2 wn = wnr[o4];
                ffma2(h2[o4 * 2 + 0], xs2, ws.x);
                ffma2(h2[o4 * 2 + 0], xm2, wn.x);
                ffma2(h2[o4 * 2 + 1], xs2, ws.y);
                ffma2(h2[o4 * 2 + 1], xm2, wn.y);
            }
        }
    }

    int g = gids[node];
#pragma unroll
    for (int o2 = 0; o2 < F / 2; o2++) {
        float lo, hi;
        unpack2(h2[o2], lo, hi);
        float v0 = fmaxf(lo + bneigh[o2 * 2 + 0], 0.0f);   // relu; >= 0
        float v1 = fmaxf(hi + bneigh[o2 * 2 + 1], 0.0f);
        atomicMax(&g_hg[g * F + o2 * 2 + 0], __float_as_int(v0));
        atomicMax(&g_hg[g * F + o2 * 2 + 1], __float_as_int(v1));
    }
}

// ---------------- [6] MLP head: one warp per graph ----------------
__global__ void __launch_bounds__(128)
k_mlp(const float* __restrict__ W1, const float* __restrict__ b1,
      const float* __restrict__ g1, const float* __restrict__ be1,
      const float* __restrict__ rm1, const float* __restrict__ rv1,
      const float* __restrict__ W2, const float* __restrict__ b2,
      const float* __restrict__ g2, const float* __restrict__ be2,
      const float* __restrict__ rm2, const float* __restrict__ rv2,
      const float* __restrict__ W3, const float* __restrict__ b3,
      float* __restrict__ out) {
    __shared__ float sh[4][F];
    __shared__ float sy[4][128];

    int w = threadIdx.x >> 5;
    int lane = threadIdx.x & 31;
    int g = blockIdx.x * 4 + w;

    sh[w][lane]      = __int_as_float(g_hg[g * F + lane]);
    sh[w][lane + 32] = __int_as_float(g_hg[g * F + lane + 32]);
    __syncwarp();

    // layer 1: 64 -> 128
    float a0 = b1[lane], a1 = b1[lane + 32], a2 = b1[lane + 64], a3 = b1[lane + 96];
#pragma unroll 8
    for (int k = 0; k < F; k++) {
        float xv = sh[w][k];
        const float* wr = &W1[k * 128 + lane];
        a0 = fmaf(xv, wr[0],  a0);
        a1 = fmaf(xv, wr[32], a1);
        a2 = fmaf(xv, wr[64], a2);
        a3 = fmaf(xv, wr[96], a3);
    }
    {
        float acc[4] = {a0, a1, a2, a3};
#pragma unroll
        for (int m = 0; m < 4; m++) {
            int j = lane + 32 * m;
            float a = fmaxf(acc[m], 0.0f);
            a = (a - rm1[j]) * rsqrtf(rv1[j] + BN_EPS) * g1[j] + be1[j];
            sy[w][j] = a;
        }
    }
    __syncwarp();

    // layer 2: 128 -> 64
    float c0 = b2[lane], c1 = b2[lane + 32];
#pragma unroll 8
    for (int k = 0; k < 128; k++) {
        float yv = sy[w][k];
        const float* wr = &W2[k * F + lane];
        c0 = fmaf(yv, wr[0],  c0);
        c1 = fmaf(yv, wr[32], c1);
    }
    float p;
    {
        int j0 = lane, j1 = lane + 32;
        float x0 = fmaxf(c0, 0.0f);
        x0 = (x0 - rm2[j0]) * rsqrtf(rv2[j0] + BN_EPS) * g2[j0] + be2[j0];
        float x1 = fmaxf(c1, 0.0f);
        x1 = (x1 - rm2[j1]) * rsqrtf(rv2[j1] + BN_EPS) * g2[j1] + be2[j1];
        p = x0 * W3[j0] + x1 * W3[j1];
    }
#pragma unroll
    for (int off = 16; off > 0; off >>= 1)
        p += __shfl_down_sync(0xFFFFFFFFu, p, off);
    if (lane == 0) out[g] = p + b3[0];
}

// ---------------- launcher ----------------
extern "C" void kernel_launch(void* const* d_in, const int* in_sizes, int n_in,
                              void* d_out, int out_size) {
    const float*  feats  = (const float*)d_in[0];
    const int*    src    = (const int*)d_in[1];
    const int*    dst    = (const int*)d_in[2];
    const int*    gids   = (const int*)d_in[3];
    const float*  Wself  = (const float*)d_in[4];
    const float*  Wneigh = (const float*)d_in[5];
    const float*  bneigh = (const float*)d_in[6];
    const float*  W1  = (const float*)d_in[7];
    const float*  b1  = (const float*)d_in[8];
    const float*  g1  = (const float*)d_in[9];
    const float*  be1 = (const float*)d_in[10];
    const float*  rm1 = (const float*)d_in[11];
    const float*  rv1 = (const float*)d_in[12];
    const float*  W2  = (const float*)d_in[13];
    const float*  b2  = (const float*)d_in[14];
    const float*  g2  = (const float*)d_in[15];
    const float*  be2 = (const float*)d_in[16];
    const float*  rm2 = (const float*)d_in[17];
    const float*  rv2 = (const float*)d_in[18];
    const float*  W3  = (const float*)d_in[19];
    const float*  b3  = (const float*)d_in[20];
    float* out = (float*)d_out;

    k_init<<<1600, 256>>>((const float2*)feats);
    k_hist<<<(N_EDGES + 255) / 256, 256>>>(dst);
    k_scan<<<SCAN_BLOCKS, 1024>>>();
    k_scatter<<<(N_EDGES + 255) / 256, 256>>>(src, dst);
    k_gather<<<(N_NODES * 8 + 255) / 256, 256>>>();
    k_node<<<(N_NODES + 255) / 256, 256>>>((const float4*)feats, Wself, Wneigh, bneigh, gids);
    k_mlp<<<N_GRAPHS / 4, 128>>>(W1, b1, g1, be1, rm1, rv1,
                                 W2, b2, g2, be2, rm2, rv2,
                                 W3, b3, out);
}